// round 4
// baseline (speedup 1.0000x reference)
#include <cuda_runtime.h>
#include <cuda_bf16.h>
#include <cstdint>

// ============================================================================
// HardMemory R3: int8 IMMA screening GEMM + exact fp32 recheck.
//   x: [32, 512, 64, 64] f32, memory: [1024, 512] f32, out like x.
// argmax_m dot(x_n, memnorm_m) is invariant to positive per-pixel scaling of x
// and to the single global scale of memnorm => quantize both to s8 with fixed
// global scales and argmax the raw s32 accumulators. Screen at 0.70*||x||
// (true threshold 0.8); flagged pixels (expected none) get exact fp32 path.
// ============================================================================

#define THRESH   0.8f
#define CDIM     512
#define HWDIM    4096
#define MMEM     1024
#define TILE_PX  128
#define NCHUNK   8
#define THREADS  512

#define XCLAMP   6.0f
#define XSCALE   (127.0f / 6.0f)
#define MSCALE   508.0f                  /* 127 / 0.25 */
#define QSCALE   9.300018e-5f            /* (6/127)*(0.25/127) */

// Prepass output: normalized memory rows quantized s8, row-major [1024][512]
__device__ __align__(16) unsigned char g_mem8[MMEM * CDIM];

// ---------------------------------------------------------------------------
// smem layout (bytes)
// ---------------------------------------------------------------------------
#define SM_X     0                       // 128px x 512B s8 (px-major, swizzled)
#define SM_B     65536                   // 2 x (128m x 512B) s8 chunk buffers
#define SM_N2    (SM_B + 131072)         // 128 f32
#define SM_RM    (SM_N2 + 512)           // 4*128 s32
#define SM_RI    (SM_RM + 2048)          // 4*128 s32
#define SM_FLAG  (SM_RI + 2048)          // 128 s32
#define SM_PASS  (SM_FLAG + 512)
#define SM_IDX   (SM_PASS + 512)
#define SM_XV    (SM_IDX + 512)          // 512 f32
#define SM_BESTU (SM_XV + 2048)
#define SM_BESTI (SM_BESTU + 4)
#define SM_TOTAL (SM_BESTI + 60)

// ---------------------------------------------------------------------------
__device__ __forceinline__ uint32_t smem_u32(const void* p) {
    uint32_t a;
    asm("{ .reg .u64 t; cvta.to.shared.u64 t, %1; cvt.u32.u64 %0, t; }"
        : "=r"(a) : "l"(p));
    return a;
}
__device__ __forceinline__ void cp_async16(uint32_t dst, const void* src) {
    asm volatile("cp.async.cg.shared.global [%0], [%1], 16;"
                 :: "r"(dst), "l"(src) : "memory");
}
#define CP_COMMIT() asm volatile("cp.async.commit_group;" ::: "memory")
#define CP_WAIT(N)  asm volatile("cp.async.wait_group %0;" :: "n"(N) : "memory")

__device__ __forceinline__ void ldsm_x4(uint32_t& r0, uint32_t& r1,
                                        uint32_t& r2, uint32_t& r3, uint32_t a) {
    asm volatile("ldmatrix.sync.aligned.m8n8.x4.shared.b16 {%0,%1,%2,%3}, [%4];"
                 : "=r"(r0), "=r"(r1), "=r"(r2), "=r"(r3) : "r"(a));
}
__device__ __forceinline__ void mma_s8(int& d0, int& d1, int& d2, int& d3,
                                       uint32_t a0, uint32_t a1, uint32_t a2, uint32_t a3,
                                       uint32_t b0, uint32_t b1) {
    asm volatile(
        "mma.sync.aligned.m16n8k32.row.col.s32.s8.s8.s32 "
        "{%0,%1,%2,%3}, {%4,%5,%6,%7}, {%8,%9}, {%0,%1,%2,%3};"
        : "+r"(d0), "+r"(d1), "+r"(d2), "+r"(d3)
        : "r"(a0), "r"(a1), "r"(a2), "r"(a3), "r"(b0), "r"(b1));
}

// Row swizzle: conflict-free for consecutive-8 rows (ldmatrix) AND stride-4
// rows (prologue transpose stores).
__device__ __forceinline__ uint32_t rowf(int r) { return (uint32_t)((r ^ (r >> 2)) & 7); }

__device__ __forceinline__ int q8x(float v) {
    return __float2int_rn(fminf(fmaxf(v, -XCLAMP), XCLAMP) * XSCALE);
}

// ---------------------------------------------------------------------------
// Prepass: memnorm = memory / max(||row||, eps) -> s8 row-major
// ---------------------------------------------------------------------------
__global__ __launch_bounds__(128) void normalize_mem_kernel(const float* __restrict__ memory) {
    const int m = blockIdx.x, tid = threadIdx.x;
    const float4 v = *(const float4*)(memory + (size_t)m * CDIM + tid * 4);
    float ss = v.x * v.x + v.y * v.y + v.z * v.z + v.w * v.w;
    #pragma unroll
    for (int o = 16; o > 0; o >>= 1) ss += __shfl_xor_sync(0xffffffffu, ss, o);
    __shared__ float ws[4];
    if ((tid & 31) == 0) ws[tid >> 5] = ss;
    __syncthreads();
    const float s = MSCALE / fmaxf(sqrtf(ws[0] + ws[1] + ws[2] + ws[3]), 1e-12f);
    int q0 = __float2int_rn(fminf(fmaxf(v.x * s, -127.f), 127.f));
    int q1 = __float2int_rn(fminf(fmaxf(v.y * s, -127.f), 127.f));
    int q2 = __float2int_rn(fminf(fmaxf(v.z * s, -127.f), 127.f));
    int q3 = __float2int_rn(fminf(fmaxf(v.w * s, -127.f), 127.f));
    const uint32_t p = (q0 & 0xff) | ((q1 & 0xff) << 8) | ((q2 & 0xff) << 16) | ((q3 & 0xff) << 24);
    *(uint32_t*)(g_mem8 + (size_t)m * CDIM + tid * 4) = p;
}

// ---------------------------------------------------------------------------
// Main kernel: 1024 CTAs x 512 thr. CTA = 128 pixels. 16 warps: 4 warp_m
// (m32 of each 128-mem chunk) x 4 warp_n (32 px). Chunks streamed whole
// (64KB) double-buffered via cp.async.
// ---------------------------------------------------------------------------
__global__ __launch_bounds__(THREADS, 1) void hardmem_main_kernel(
    const float* __restrict__ x,
    const float* __restrict__ memory,
    float* __restrict__ out)
{
    extern __shared__ char smem[];
    const uint32_t smx = smem_u32(smem);
    const int tid = threadIdx.x;
    const int lane = tid & 31;
    const int wid = tid >> 5;
    const int warp_m = wid >> 2;
    const int warp_n = wid & 3;
    const int b  = blockIdx.x >> 5;
    const int n0 = (blockIdx.x & 31) << 7;

    float* s_n2   = (float*)(smem + SM_N2);
    int*   s_rm   = (int*)(smem + SM_RM);
    int*   s_ri   = (int*)(smem + SM_RI);
    int*   s_flag = (int*)(smem + SM_FLAG);
    int*   s_pass = (int*)(smem + SM_PASS);
    int*   s_idx  = (int*)(smem + SM_IDX);
    float* s_xv   = (float*)(smem + SM_XV);
    unsigned* s_bestu = (unsigned*)(smem + SM_BESTU);
    int*      s_besti = (int*)(smem + SM_BESTI);

    if (tid < TILE_PX) s_n2[tid] = 0.0f;

    // ---- prefetch memnorm chunk 0 (64KB) ----
    {
        #pragma unroll
        for (int i = 0; i < 8; ++i) {
            const int j = tid + i * THREADS;
            const int m = j >> 5, g = j & 31;
            cp_async16(smx + SM_B + m * 512 + (((g ^ rowf(m)) & 31) << 4),
                       g_mem8 + (size_t)m * 512 + (size_t)g * 16);
        }
        CP_COMMIT();
    }

    // ---- x tile: read fp32 (coalesced over px), quantize s8, register
    //      transpose 4x4, store px-major [128][512B] swizzled ----
    {
        const float* xb = x + (size_t)b * CDIM * HWDIM + n0;
        const int px4 = lane << 2;
        float acc[4] = {0.f, 0.f, 0.f, 0.f};
        #pragma unroll 2
        for (int g = 0; g < 8; ++g) {
            const int k0 = (g * 16 + wid) * 4;
            float4 v[4];
            #pragma unroll
            for (int kk = 0; kk < 4; ++kk)
                v[kk] = *(const float4*)(xb + (size_t)(k0 + kk) * HWDIM + px4);
            #pragma unroll
            for (int j = 0; j < 4; ++j) {
                const float c0 = ((const float*)&v[0])[j];
                const float c1 = ((const float*)&v[1])[j];
                const float c2 = ((const float*)&v[2])[j];
                const float c3 = ((const float*)&v[3])[j];
                acc[j] += c0 * c0 + c1 * c1 + c2 * c2 + c3 * c3;
                const uint32_t p = (q8x(c0) & 0xff) | ((q8x(c1) & 0xff) << 8) |
                                   ((q8x(c2) & 0xff) << 16) | ((q8x(c3) & 0xff) << 24);
                const int px = px4 + j;
                *(uint32_t*)(smem + SM_X + px * 512 +
                             ((((uint32_t)(k0 >> 4) ^ rowf(px)) & 31) << 4) + (k0 & 15)) = p;
            }
        }
        #pragma unroll
        for (int j = 0; j < 4; ++j) atomicAdd(&s_n2[px4 + j], acc[j]);
    }

    // ---- per-lane ldmatrix address components ----
    const int a_row0 = warp_m * 32 + (lane & 15);                  // + mt*16
    const uint32_t a_hi = (uint32_t)(lane >> 4);
    const int b_row0 = warp_n * 32 + (lane & 7) + ((lane >> 4) << 3);  // + nt16*16
    const uint32_t b_hi = (uint32_t)((lane >> 3) & 1);

    uint32_t aB[2], fA[2], bB[2], fB[2];
    #pragma unroll
    for (int mt = 0; mt < 2; ++mt) {
        const int r = a_row0 + mt * 16;
        aB[mt] = r * 512; fA[mt] = rowf(r);
    }
    #pragma unroll
    for (int nh = 0; nh < 2; ++nh) {
        const int r = b_row0 + nh * 16;
        bB[nh] = smx + SM_X + r * 512; fB[nh] = rowf(r);
    }

    int rmax[8], ridx[8];
    #pragma unroll
    for (int s = 0; s < 8; ++s) { rmax[s] = -0x7fffffff; ridx[s] = 0; }

    // ---- mainloop over 8 memnorm chunks ----
    for (int t = 0; t < NCHUNK; ++t) {
        if (t + 1 < NCHUNK) {
            const unsigned char* src = g_mem8 + (size_t)(t + 1) * (128 * 512);
            const uint32_t dstb = smx + SM_B + ((t + 1) & 1) * 65536;
            #pragma unroll
            for (int i = 0; i < 8; ++i) {
                const int j = tid + i * THREADS;
                const int m = j >> 5, g = j & 31;
                cp_async16(dstb + m * 512 + (((g ^ rowf(m)) & 31) << 4),
                           src + (size_t)m * 512 + (size_t)g * 16);
            }
            CP_COMMIT();
            CP_WAIT(1);
        } else {
            CP_WAIT(0);
        }
        __syncthreads();

        const uint32_t abuf = smx + SM_B + (t & 1) * 65536;
        int d[2][4][4];
        #pragma unroll
        for (int mt = 0; mt < 2; ++mt)
            #pragma unroll
            for (int nt = 0; nt < 4; ++nt)
                #pragma unroll
                for (int r = 0; r < 4; ++r) d[mt][nt][r] = 0;

        #pragma unroll
        for (int ks = 0; ks < 16; ++ks) {
            uint32_t a[2][4];
            #pragma unroll
            for (int mt = 0; mt < 2; ++mt)
                ldsm_x4(a[mt][0], a[mt][1], a[mt][2], a[mt][3],
                        abuf + aB[mt] + (((((uint32_t)ks << 1) | a_hi) ^ fA[mt]) << 4));
            uint32_t bq[2][4];
            #pragma unroll
            for (int nh = 0; nh < 2; ++nh)
                ldsm_x4(bq[nh][0], bq[nh][1], bq[nh][2], bq[nh][3],
                        bB[nh] + (((((uint32_t)ks << 1) | b_hi) ^ fB[nh]) << 4));
            #pragma unroll
            for (int mt = 0; mt < 2; ++mt)
                #pragma unroll
                for (int nt = 0; nt < 4; ++nt)
                    mma_s8(d[mt][nt][0], d[mt][nt][1], d[mt][nt][2], d[mt][nt][3],
                           a[mt][0], a[mt][1], a[mt][2], a[mt][3],
                           bq[nt >> 1][(nt & 1) * 2], bq[nt >> 1][(nt & 1) * 2 + 1]);
        }

        // fold chunk into running s32 max (ascending mem index within slot)
        const int mem_base = t * 128 + warp_m * 32 + (lane >> 2);
        #pragma unroll
        for (int nt = 0; nt < 4; ++nt)
            #pragma unroll
            for (int sub = 0; sub < 2; ++sub) {
                const int s = nt * 2 + sub;
                #pragma unroll
                for (int mt = 0; mt < 2; ++mt)
                    #pragma unroll
                    for (int rh = 0; rh < 2; ++rh) {
                        const int v = d[mt][nt][rh * 2 + sub];
                        const int mi = mem_base + mt * 16 + rh * 8;
                        if (v > rmax[s]) { rmax[s] = v; ridx[s] = mi; }
                    }
            }
        __syncthreads();
    }

    // ---- cross-lane reduce (rows on lanes stride 4) ----
    #pragma unroll
    for (int o = 4; o <= 16; o <<= 1)
        #pragma unroll
        for (int s = 0; s < 8; ++s) {
            const int om = __shfl_xor_sync(0xffffffffu, rmax[s], o);
            const int oi = __shfl_xor_sync(0xffffffffu, ridx[s], o);
            if (om > rmax[s] || (om == rmax[s] && oi < ridx[s])) { rmax[s] = om; ridx[s] = oi; }
        }
    if (lane < 4) {
        #pragma unroll
        for (int s = 0; s < 8; ++s) {
            const int col = warp_n * 32 + (s >> 1) * 8 + lane * 2 + (s & 1);
            s_rm[warp_m * 128 + col] = rmax[s];
            s_ri[warp_m * 128 + col] = ridx[s];
        }
    }
    __syncthreads();

    // ---- per-pixel decision: screen at 0.70 (true 0.80), flag gray-zone ----
    if (tid < TILE_PX) {
        int bv = s_rm[tid], bi = s_ri[tid];
        #pragma unroll
        for (int g = 1; g < 4; ++g) {
            const int v = s_rm[g * 128 + tid], i = s_ri[g * 128 + tid];
            if (v > bv || (v == bv && i < bi)) { bv = v; bi = i; }
        }
        const float nx = fmaxf(sqrtf(s_n2[tid]), 1e-12f);
        s_flag[tid] = ((float)bv * QSCALE > 0.70f * nx) ? 1 : 0;
        s_pass[tid] = 0;
        s_idx[tid]  = bi;
    }
    __syncthreads();

    // ---- exact fp32 path for flagged pixels (expected: none) ----
    for (int px = 0; px < TILE_PX; ++px) {
        if (!s_flag[px]) continue;
        for (int c = tid; c < CDIM; c += THREADS)
            s_xv[c] = x[(size_t)b * CDIM * HWDIM + (size_t)c * HWDIM + n0 + px];
        if (tid == 0) { *s_bestu = 0u; *s_besti = 0x7fffffff; }
        __syncthreads();
        float lb = -3.0e38f; int li = 0x7fffffff;
        #pragma unroll 1
        for (int mm = tid * 2; mm < tid * 2 + 2; ++mm) {
            const float* mr = memory + (size_t)mm * CDIM;
            float dot = 0.f, nn = 0.f;
            for (int c = 0; c < CDIM; ++c) { const float mv = mr[c]; dot += s_xv[c] * mv; nn += mv * mv; }
            const float v = dot / fmaxf(sqrtf(nn), 1e-12f);
            if (v > lb) { lb = v; li = mm; }
        }
        unsigned enc = __float_as_uint(lb);
        enc = (enc & 0x80000000u) ? ~enc : (enc | 0x80000000u);
        atomicMax(s_bestu, enc);
        __syncthreads();
        if (enc == *s_bestu) atomicMin(s_besti, li);
        __syncthreads();
        if (tid == 0) {
            unsigned u = *s_bestu;
            const float bvf = __uint_as_float((u & 0x80000000u) ? (u & 0x7fffffffu) : ~u);
            const float nx = fmaxf(sqrtf(s_n2[px]), 1e-12f);
            s_pass[px] = (bvf > THRESH * nx) ? 1 : 0;
            s_idx[px]  = *s_besti;
        }
        __syncthreads();
    }
    __syncthreads();

    // ---- writeback: full tile, coalesced (zeros or gathered memory row) ----
    {
        const int pxl = tid & 127;
        const int c0  = tid >> 7;
        const int pass = s_pass[pxl];
        const float* mrow = memory + (size_t)s_idx[pxl] * CDIM;
        float* ob = out + (size_t)b * CDIM * HWDIM + n0 + pxl;
        #pragma unroll 8
        for (int c = c0; c < CDIM; c += 4)
            ob[(size_t)c * HWDIM] = pass ? mrow[c] : 0.0f;
    }
}

// ---------------------------------------------------------------------------
extern "C" void kernel_launch(void* const* d_in, const int* in_sizes, int n_in,
                              void* d_out, int out_size) {
    const float* x      = (const float*)d_in[0];
    const float* memory = (const float*)d_in[1];
    float* out          = (float*)d_out;

    cudaFuncSetAttribute(hardmem_main_kernel,
                         cudaFuncAttributeMaxDynamicSharedMemorySize, SM_TOTAL);

    normalize_mem_kernel<<<MMEM, 128>>>(memory);
    hardmem_main_kernel<<<32 * (HWDIM / TILE_PX), THREADS, SM_TOTAL>>>(x, memory, out);
}

// round 8
// speedup vs baseline: 2.1615x; 2.1615x over previous
#include <cuda_runtime.h>
#include <cuda_fp16.h>
#include <cstdint>

// ============================================================================
// HardMemory R4: fp16 HMMA (f16 accum) screening GEMM + exact fp32 recheck.
//   x: [32, 512, 64, 64] f32, memory: [1024, 512] f32, out like x.
// mask_n = (max_m dot(x_n, memnorm_m) > 0.8*max(||x_n||,eps)); out = mask ?
// memory[argmax] : 0. Screen in fp16 at 0.70*||x||; flagged pixels (expected
// none) re-checked exactly in fp32. Legacy IMMA s8 is ~8x slower than HMMA on
// sm_103 (R3 measurement) -> fp16 HMMA with f16 accumulators (2x f32-accum).
// ============================================================================

#define THRESH   0.8f
#define CDIM     512
#define HWDIM    4096
#define MMEM     1024
#define TILE_PX  128
#define THREADS  512

// Prepass output: normalized memory rows, fp16, row-major [1024][512]
__device__ __align__(16) unsigned char g_memh[MMEM * CDIM * 2];

// ---------------------------------------------------------------------------
// smem layout (bytes)
// ---------------------------------------------------------------------------
#define SM_X     0                        // [512 k][256B px-fp16] = 131072
#define SM_B     131072                   // 2 x [128 m][256B k-fp16] = 65536
#define SM_N2    (SM_B + 65536)           // 128 f32
#define SM_RM    (SM_N2 + 512)            // 4*128 f32
#define SM_RI    (SM_RM + 2048)           // 4*128 i32
#define SM_FLAG  (SM_RI + 2048)           // 128 i32
#define SM_PASS  (SM_FLAG + 512)
#define SM_IDX   (SM_PASS + 512)
#define SM_XV    (SM_IDX + 512)           // 512 f32
#define SM_BESTU (SM_XV + 2048)
#define SM_BESTI (SM_BESTU + 4)
#define SM_TOTAL (SM_BESTI + 60)

// ---------------------------------------------------------------------------
__device__ __forceinline__ uint32_t smem_u32(const void* p) {
    uint32_t a;
    asm("{ .reg .u64 t; cvta.to.shared.u64 t, %1; cvt.u32.u64 %0, t; }"
        : "=r"(a) : "l"(p));
    return a;
}
__device__ __forceinline__ void cp_async16(uint32_t dst, const void* src) {
    asm volatile("cp.async.cg.shared.global [%0], [%1], 16;"
                 :: "r"(dst), "l"(src) : "memory");
}
#define CP_COMMIT() asm volatile("cp.async.commit_group;" ::: "memory")
#define CP_WAIT(N)  asm volatile("cp.async.wait_group %0;" :: "n"(N) : "memory")

__device__ __forceinline__ void ldsm_x4(uint32_t& r0, uint32_t& r1,
                                        uint32_t& r2, uint32_t& r3, uint32_t a) {
    asm volatile("ldmatrix.sync.aligned.m8n8.x4.shared.b16 {%0,%1,%2,%3}, [%4];"
                 : "=r"(r0), "=r"(r1), "=r"(r2), "=r"(r3) : "r"(a));
}
__device__ __forceinline__ void ldsm_x4t(uint32_t& r0, uint32_t& r1,
                                         uint32_t& r2, uint32_t& r3, uint32_t a) {
    asm volatile("ldmatrix.sync.aligned.m8n8.x4.trans.shared.b16 {%0,%1,%2,%3}, [%4];"
                 : "=r"(r0), "=r"(r1), "=r"(r2), "=r"(r3) : "r"(a));
}
// fp16 in, fp16 accum (2 dst regs = 4 halves)
__device__ __forceinline__ void mma_h(uint32_t& d0, uint32_t& d1,
                                      uint32_t a0, uint32_t a1, uint32_t a2, uint32_t a3,
                                      uint32_t b0, uint32_t b1) {
    asm volatile(
        "mma.sync.aligned.m16n8k16.row.col.f16.f16.f16.f16 "
        "{%0,%1}, {%2,%3,%4,%5}, {%6,%7}, {%0,%1};"
        : "+r"(d0), "+r"(d1)
        : "r"(a0), "r"(a1), "r"(a2), "r"(a3), "r"(b0), "r"(b1));
}

// ---------------------------------------------------------------------------
// Prepass: memnorm = memory / max(||row||, eps) -> fp16 row-major
// ---------------------------------------------------------------------------
__global__ __launch_bounds__(128) void normalize_mem_kernel(const float* __restrict__ memory) {
    const int m = blockIdx.x, tid = threadIdx.x;
    const float4 v = *(const float4*)(memory + (size_t)m * CDIM + tid * 4);
    float ss = v.x * v.x + v.y * v.y + v.z * v.z + v.w * v.w;
    #pragma unroll
    for (int o = 16; o > 0; o >>= 1) ss += __shfl_xor_sync(0xffffffffu, ss, o);
    __shared__ float ws[4];
    if ((tid & 31) == 0) ws[tid >> 5] = ss;
    __syncthreads();
    const float s = 1.0f / fmaxf(sqrtf(ws[0] + ws[1] + ws[2] + ws[3]), 1e-12f);
    uint32_t p0 = __half_as_ushort(__float2half_rn(v.x * s)) |
                  ((uint32_t)__half_as_ushort(__float2half_rn(v.y * s)) << 16);
    uint32_t p1 = __half_as_ushort(__float2half_rn(v.z * s)) |
                  ((uint32_t)__half_as_ushort(__float2half_rn(v.w * s)) << 16);
    *(uint2*)(g_memh + (size_t)m * (CDIM * 2) + tid * 8) = make_uint2(p0, p1);
}

// ---------------------------------------------------------------------------
// Main kernel: 1024 CTAs x 512 thr (16 warps). CTA = 128 pixels.
// Warp grid 4 warp_m (m32 of 128-mem chunk) x 4 warp_n (32 px).
// B streamed as 32 slices of [128 m][128 k] fp16 (32KB) double-buffered.
// ---------------------------------------------------------------------------
__global__ __launch_bounds__(THREADS, 1) void hardmem_main_kernel(
    const float* __restrict__ x,
    const float* __restrict__ memory,
    float* __restrict__ out)
{
    extern __shared__ char smem[];
    const uint32_t smx = smem_u32(smem);
    const int tid = threadIdx.x;
    const int lane = tid & 31;
    const int wid = tid >> 5;
    const int warp_m = wid >> 2;        // 0..3
    const int warp_n = wid & 3;         // 0..3
    const int b  = blockIdx.x >> 5;
    const int n0 = (blockIdx.x & 31) << 7;

    float* s_n2   = (float*)(smem + SM_N2);
    float* s_rm   = (float*)(smem + SM_RM);
    int*   s_ri   = (int*)(smem + SM_RI);
    int*   s_flag = (int*)(smem + SM_FLAG);
    int*   s_pass = (int*)(smem + SM_PASS);
    int*   s_idx  = (int*)(smem + SM_IDX);
    float* s_xv   = (float*)(smem + SM_XV);
    unsigned* s_bestu = (unsigned*)(smem + SM_BESTU);
    int*      s_besti = (int*)(smem + SM_BESTI);

    if (tid < TILE_PX) s_n2[tid] = 0.0f;

    // ---- prefetch B slice 0 (chunk 0, k 0..127) ----
    {
        #pragma unroll
        for (int i = 0; i < 4; ++i) {
            const int j = tid + i * THREADS;          // 2048 granules of 16B
            const int m = j >> 4, g = j & 15;
            cp_async16(smx + SM_B + m * 256 + (((uint32_t)g ^ (uint32_t)(m & 7)) << 4),
                       g_memh + (size_t)m * 1024 + (size_t)g * 16);
        }
        CP_COMMIT();
    }

    // ---- resident x tile: [512 k][128 px] fp16, coalesced fp32 reads ----
    {
        const float* xb = x + (size_t)b * CDIM * HWDIM + n0;
        const int px4 = lane << 2;                 // 4 fixed pixels per lane
        float ss0 = 0.f, ss1 = 0.f, ss2 = 0.f, ss3 = 0.f;
        #pragma unroll 8
        for (int it = 0; it < 32; ++it) {
            const int k = wid + it * 16;
            const float4 v = *(const float4*)(xb + (size_t)k * HWDIM + px4);
            ss0 += v.x * v.x; ss1 += v.y * v.y; ss2 += v.z * v.z; ss3 += v.w * v.w;
            uint32_t p0 = __half_as_ushort(__float2half_rn(v.x)) |
                          ((uint32_t)__half_as_ushort(__float2half_rn(v.y)) << 16);
            uint32_t p1 = __half_as_ushort(__float2half_rn(v.z)) |
                          ((uint32_t)__half_as_ushort(__float2half_rn(v.w)) << 16);
            const uint32_t a = (uint32_t)(k << 8) + (((uint32_t)(px4 << 1)) ^ ((k & 7) << 4));
            *(uint2*)(smem + SM_X + a) = make_uint2(p0, p1);
        }
        atomicAdd(&s_n2[px4 + 0], ss0);
        atomicAdd(&s_n2[px4 + 1], ss1);
        atomicAdd(&s_n2[px4 + 2], ss2);
        atomicAdd(&s_n2[px4 + 3], ss3);
    }

    // ---- ldmatrix lane addressing ----
    const int lr = lane & 7;
    const int lh = (lane >> 3) & 1;
    const uint32_t a_hi = (uint32_t)(lane >> 4);
    // A rows: warp_m*32 + mt*16 + (lane&15)
    uint32_t aB[2], fA[2];
    #pragma unroll
    for (int mt = 0; mt < 2; ++mt) {
        const int r = warp_m * 32 + mt * 16 + (lane & 15);
        aB[mt] = (uint32_t)(r << 8);
        fA[mt] = (uint32_t)(r & 7);
    }
    // B (x tile, trans): krow = lr + lh*8 ; px = warp_n*32 + lq*8 (+16)
    const uint32_t krow   = (uint32_t)(lr + lh * 8);
    const uint32_t px2    = (uint32_t)((warp_n * 32 + ((lane >> 4) & 1) * 8) * 2);
    const uint32_t pxoff0 = px2 ^ ((uint32_t)lr << 4);
    const uint32_t pxoff1 = (px2 + 32) ^ ((uint32_t)lr << 4);

    float rmax[8];
    int   ridx[8];
    #pragma unroll
    for (int s = 0; s < 8; ++s) { rmax[s] = -3.0e38f; ridx[s] = 0; }

    uint32_t d[2][4][2];                 // [mt][nt][reg] fp16x2 accum

    // ---- mainloop: 32 slices = 8 chunks x 4 k-slices ----
    for (int ts = 0; ts < 32; ++ts) {
        if (ts + 1 < 32) {
            const int nt2 = ts + 1;
            const unsigned char* src = g_memh +
                (size_t)(nt2 >> 2) * (128 * 1024) + (size_t)(nt2 & 3) * 256;
            const uint32_t dstb = smx + SM_B + (nt2 & 1) * 32768;
            #pragma unroll
            for (int i = 0; i < 4; ++i) {
                const int j = tid + i * THREADS;
                const int m = j >> 4, g = j & 15;
                cp_async16(dstb + m * 256 + (((uint32_t)g ^ (uint32_t)(m & 7)) << 4),
                           src + (size_t)m * 1024 + (size_t)g * 16);
            }
            CP_COMMIT();
            CP_WAIT(1);
        } else {
            CP_WAIT(0);
        }
        __syncthreads();

        if ((ts & 3) == 0) {
            #pragma unroll
            for (int mt = 0; mt < 2; ++mt)
                #pragma unroll
                for (int nt = 0; nt < 4; ++nt)
                    d[mt][nt][0] = d[mt][nt][1] = 0u;
        }

        const uint32_t abuf = smx + SM_B + (ts & 1) * 32768;
        const uint32_t kbase = (uint32_t)((ts & 3) * 128);

        #pragma unroll
        for (int ks = 0; ks < 8; ++ks) {
            uint32_t a[2][4];
            #pragma unroll
            for (int mt = 0; mt < 2; ++mt)
                ldsm_x4(a[mt][0], a[mt][1], a[mt][2], a[mt][3],
                        abuf + aB[mt] + (((((uint32_t)ks << 1) | a_hi) ^ fA[mt]) << 4));
            uint32_t bq[8];
            const uint32_t brow = smx + SM_X + (kbase + (uint32_t)(ks * 16) + krow) * 256;
            ldsm_x4t(bq[0], bq[1], bq[2], bq[3], brow + pxoff0);
            ldsm_x4t(bq[4], bq[5], bq[6], bq[7], brow + pxoff1);
            #pragma unroll
            for (int mt = 0; mt < 2; ++mt)
                #pragma unroll
                for (int nt = 0; nt < 4; ++nt)
                    mma_h(d[mt][nt][0], d[mt][nt][1],
                          a[mt][0], a[mt][1], a[mt][2], a[mt][3],
                          bq[(nt >> 1) * 4 + (nt & 1) * 2],
                          bq[(nt >> 1) * 4 + (nt & 1) * 2 + 1]);
        }

        if ((ts & 3) == 3) {             // chunk done: fold into running max
            const int mem_base = (ts >> 2) * 128 + warp_m * 32 + (lane >> 2);
            #pragma unroll
            for (int nt = 0; nt < 4; ++nt)
                #pragma unroll
                for (int rh = 0; rh < 2; ++rh) {
                    #pragma unroll
                    for (int mt = 0; mt < 2; ++mt) {
                        const float2 f = __half22float2(*(const __half2*)&d[mt][nt][rh]);
                        const int mi = mem_base + mt * 16 + rh * 8;
                        const int s0 = nt * 2;
                        if (f.x > rmax[s0])     { rmax[s0]     = f.x; ridx[s0]     = mi; }
                        if (f.y > rmax[s0 + 1]) { rmax[s0 + 1] = f.y; ridx[s0 + 1] = mi; }
                    }
                }
        }
        __syncthreads();
    }

    // ---- cross-lane reduce (rows live on lanes stride 4) ----
    #pragma unroll
    for (int o = 4; o <= 16; o <<= 1)
        #pragma unroll
        for (int s = 0; s < 8; ++s) {
            const float om = __shfl_xor_sync(0xffffffffu, rmax[s], o);
            const int   oi = __shfl_xor_sync(0xffffffffu, ridx[s], o);
            if (om > rmax[s] || (om == rmax[s] && oi < ridx[s])) { rmax[s] = om; ridx[s] = oi; }
        }
    if (lane < 4) {
        #pragma unroll
        for (int s = 0; s < 8; ++s) {
            const int col = warp_n * 32 + (s >> 1) * 8 + lane * 2 + (s & 1);
            s_rm[warp_m * 128 + col] = rmax[s];
            s_ri[warp_m * 128 + col] = ridx[s];
        }
    }
    __syncthreads();

    // ---- per-pixel decision: screen at 0.70 (true 0.80) ----
    if (tid < TILE_PX) {
        float bv = s_rm[tid]; int bi = s_ri[tid];
        #pragma unroll
        for (int g = 1; g < 4; ++g) {
            const float v = s_rm[g * 128 + tid]; const int i = s_ri[g * 128 + tid];
            if (v > bv || (v == bv && i < bi)) { bv = v; bi = i; }
        }
        const float nx = fmaxf(sqrtf(s_n2[tid]), 1e-12f);
        s_flag[tid] = (bv > 0.70f * nx) ? 1 : 0;
        s_pass[tid] = 0;
        s_idx[tid]  = bi;
    }
    __syncthreads();

    // ---- exact fp32 path for flagged pixels (expected: none) ----
    for (int px = 0; px < TILE_PX; ++px) {
        if (!s_flag[px]) continue;
        for (int c = tid; c < CDIM; c += THREADS)
            s_xv[c] = x[(size_t)b * CDIM * HWDIM + (size_t)c * HWDIM + n0 + px];
        if (tid == 0) { *s_bestu = 0u; *s_besti = 0x7fffffff; }
        __syncthreads();
        float lb = -3.0e38f; int li = 0x7fffffff;
        #pragma unroll 1
        for (int mm = tid * 2; mm < tid * 2 + 2; ++mm) {
            const float* mr = memory + (size_t)mm * CDIM;
            float dot = 0.f, nn = 0.f;
            for (int c = 0; c < CDIM; ++c) { const float mv = mr[c]; dot += s_xv[c] * mv; nn += mv * mv; }
            const float v = dot / fmaxf(sqrtf(nn), 1e-12f);
            if (v > lb) { lb = v; li = mm; }
        }
        unsigned enc = __float_as_uint(lb);
        enc = (enc & 0x80000000u) ? ~enc : (enc | 0x80000000u);
        atomicMax(s_bestu, enc);
        __syncthreads();
        if (enc == *s_bestu) atomicMin(s_besti, li);
        __syncthreads();
        if (tid == 0) {
            unsigned u = *s_bestu;
            const float bvf = __uint_as_float((u & 0x80000000u) ? (u & 0x7fffffffu) : ~u);
            const float nx = fmaxf(sqrtf(s_n2[px]), 1e-12f);
            s_pass[px] = (bvf > THRESH * nx) ? 1 : 0;
            s_idx[px]  = *s_besti;
        }
        __syncthreads();
    }
    __syncthreads();

    // ---- writeback: full tile, coalesced ----
    {
        const int pxl = tid & 127;
        const int c0  = tid >> 7;
        const int pass = s_pass[pxl];
        const float* mrow = memory + (size_t)s_idx[pxl] * CDIM;
        float* ob = out + (size_t)b * CDIM * HWDIM + n0 + pxl;
        #pragma unroll 8
        for (int c = c0; c < CDIM; c += 4)
            ob[(size_t)c * HWDIM] = pass ? mrow[c] : 0.0f;
    }
}

// ---------------------------------------------------------------------------
extern "C" void kernel_launch(void* const* d_in, const int* in_sizes, int n_in,
                              void* d_out, int out_size) {
    const float* x      = (const float*)d_in[0];
    const float* memory = (const float*)d_in[1];
    float* out          = (float*)d_out;

    cudaFuncSetAttribute(hardmem_main_kernel,
                         cudaFuncAttributeMaxDynamicSharedMemorySize, SM_TOTAL);

    normalize_mem_kernel<<<MMEM, 128>>>(memory);
    hardmem_main_kernel<<<32 * (HWDIM / TILE_PX), THREADS, SM_TOTAL>>>(x, memory, out);
}

// round 10
// speedup vs baseline: 3.4146x; 1.5797x over previous
#include <cuda_runtime.h>
#include <cuda_fp16.h>
#include <cstdint>

// ============================================================================
// HardMemory R9: K-halved fp16 HMMA screen via Cauchy-Schwarz upper bound.
//   x: [32, 512, 64, 64] f32, memory: [1024, 512] f32, out like x.
// cos(x, m_hat) = dot1(x1,m1_hat)/||x|| + dot2/||x||
//   <= (dot1 + ||x2||*Bmax)/||x||,  Bmax = max_m ||m2_hat|| (prepass scalar).
// GEMM over K=256 only; flag pixel iff dot1max + ||x2||*Bmax > 0.75*||x||
// (true threshold 0.8). Flagged pixels (expected: none) -> exact fp32 path,
// which also computes the true argmax. GEMM needs max only, no argmax.
// R2/R4 evidence: mma.sync HMMA count is the wall on sm_103 -> halve it.
// ============================================================================

#define THRESH   0.8f
#define CDIM     512
#define KGEMM    256
#define HWDIM    4096
#define MMEM     1024
#define TILE_PX  128
#define THREADS  512

// Prepass: normalized memory rows, first 256 channels, fp16 [1024][256]
__device__ __align__(16) unsigned char g_memh[MMEM * KGEMM * 2];
__device__ float g_bmax;   // max over rows of ||m_hat[256:512]|| (zero-init)

// ---------------------------------------------------------------------------
// smem layout (bytes)
// ---------------------------------------------------------------------------
#define SM_X     0                        // [256 k][256B px-fp16] = 65536
#define SM_B     65536                    // 2 x [512 m][128B k-fp16] = 131072
#define SM_N2    (SM_B + 131072)          // 128 f32 full ||x||^2
#define SM_T2    (SM_N2 + 512)            // 128 f32 tail ||x2||^2
#define SM_RM    (SM_T2 + 512)            // 8*128 f32
#define SM_FLAG  (SM_RM + 4096)           // 128 i32
#define SM_PASS  (SM_FLAG + 512)
#define SM_IDX   (SM_PASS + 512)
#define SM_XV    (SM_IDX + 512)           // 512 f32
#define SM_BESTU (SM_XV + 2048)
#define SM_BESTI (SM_BESTU + 4)
#define SM_TOTAL (SM_BESTI + 60)

// ---------------------------------------------------------------------------
__device__ __forceinline__ uint32_t smem_u32(const void* p) {
    uint32_t a;
    asm("{ .reg .u64 t; cvta.to.shared.u64 t, %1; cvt.u32.u64 %0, t; }"
        : "=r"(a) : "l"(p));
    return a;
}
__device__ __forceinline__ void cp_async16(uint32_t dst, const void* src) {
    asm volatile("cp.async.cg.shared.global [%0], [%1], 16;"
                 :: "r"(dst), "l"(src) : "memory");
}
#define CP_COMMIT() asm volatile("cp.async.commit_group;" ::: "memory")
#define CP_WAIT(N)  asm volatile("cp.async.wait_group %0;" :: "n"(N) : "memory")

__device__ __forceinline__ void ldsm_x4(uint32_t& r0, uint32_t& r1,
                                        uint32_t& r2, uint32_t& r3, uint32_t a) {
    asm volatile("ldmatrix.sync.aligned.m8n8.x4.shared.b16 {%0,%1,%2,%3}, [%4];"
                 : "=r"(r0), "=r"(r1), "=r"(r2), "=r"(r3) : "r"(a));
}
__device__ __forceinline__ void ldsm_x4t(uint32_t& r0, uint32_t& r1,
                                         uint32_t& r2, uint32_t& r3, uint32_t a) {
    asm volatile("ldmatrix.sync.aligned.m8n8.x4.trans.shared.b16 {%0,%1,%2,%3}, [%4];"
                 : "=r"(r0), "=r"(r1), "=r"(r2), "=r"(r3) : "r"(a));
}
__device__ __forceinline__ void mma_h(uint32_t& d0, uint32_t& d1,
                                      uint32_t a0, uint32_t a1, uint32_t a2, uint32_t a3,
                                      uint32_t b0, uint32_t b1) {
    asm volatile(
        "mma.sync.aligned.m16n8k16.row.col.f16.f16.f16.f16 "
        "{%0,%1}, {%2,%3,%4,%5}, {%6,%7}, {%0,%1};"
        : "+r"(d0), "+r"(d1)
        : "r"(a0), "r"(a1), "r"(a2), "r"(a3), "r"(b0), "r"(b1));
}
__device__ __forceinline__ uint32_t hmax2u(uint32_t a, uint32_t b) {
    const __half2 r = __hmax2(*(const __half2*)&a, *(const __half2*)&b);
    return *(const uint32_t*)&r;
}

// ---------------------------------------------------------------------------
// Prepass: m_hat = memory/max(||row||,eps); store m_hat[0:256] fp16;
// atomicMax ||m_hat[256:512]|| into g_bmax (idempotent across graph replays).
// ---------------------------------------------------------------------------
__global__ __launch_bounds__(128) void normalize_mem_kernel(const float* __restrict__ memory) {
    const int m = blockIdx.x, tid = threadIdx.x;
    const float4 v = *(const float4*)(memory + (size_t)m * CDIM + tid * 4);
    float ss = v.x * v.x + v.y * v.y + v.z * v.z + v.w * v.w;
    #pragma unroll
    for (int o = 16; o > 0; o >>= 1) ss += __shfl_xor_sync(0xffffffffu, ss, o);
    __shared__ float ws[4];
    if ((tid & 31) == 0) ws[tid >> 5] = ss;
    __syncthreads();
    const float tot  = ws[0] + ws[1] + ws[2] + ws[3];
    const float tail = ws[2] + ws[3];                 // k in [256, 512)
    const float s = 1.0f / fmaxf(sqrtf(tot), 1e-12f);
    if (tid < 64) {                                   // k < 256: store fp16
        uint32_t p0 = __half_as_ushort(__float2half_rn(v.x * s)) |
                      ((uint32_t)__half_as_ushort(__float2half_rn(v.y * s)) << 16);
        uint32_t p1 = __half_as_ushort(__float2half_rn(v.z * s)) |
                      ((uint32_t)__half_as_ushort(__float2half_rn(v.w * s)) << 16);
        *(uint2*)(g_memh + (size_t)m * (KGEMM * 2) + tid * 8) = make_uint2(p0, p1);
    }
    if (tid == 0) {
        const float tn = sqrtf(tail) * s;             // ||m_hat tail|| (>= 0)
        atomicMax((unsigned*)&g_bmax, __float_as_uint(tn));
    }
}

// ---------------------------------------------------------------------------
// Main: 1024 CTAs x 512 thr. 16 warps = 8 warp_m (m64) x 2 warp_n (n64).
// Chunk = 512 mem rows (2 chunks). B slices [512 m][64 k] fp16 = 64KB, x2 buf.
// ---------------------------------------------------------------------------
__global__ __launch_bounds__(THREADS, 1) void hardmem_main_kernel(
    const float* __restrict__ x,
    const float* __restrict__ memory,
    float* __restrict__ out)
{
    extern __shared__ char smem[];
    const uint32_t smx = smem_u32(smem);
    const int tid = threadIdx.x;
    const int lane = tid & 31;
    const int wid = tid >> 5;
    const int warp_m = wid >> 1;        // 0..7 -> m64 within 512-chunk
    const int warp_n = wid & 1;         // 0..1 -> px64
    const int b  = blockIdx.x >> 5;
    const int n0 = (blockIdx.x & 31) << 7;

    float* s_n2   = (float*)(smem + SM_N2);
    float* s_t2   = (float*)(smem + SM_T2);
    float* s_rm   = (float*)(smem + SM_RM);
    int*   s_flag = (int*)(smem + SM_FLAG);
    int*   s_pass = (int*)(smem + SM_PASS);
    int*   s_idx  = (int*)(smem + SM_IDX);
    float* s_xv   = (float*)(smem + SM_XV);
    unsigned* s_bestu = (unsigned*)(smem + SM_BESTU);
    int*      s_besti = (int*)(smem + SM_BESTI);

    if (tid < TILE_PX) { s_n2[tid] = 0.0f; s_t2[tid] = 0.0f; }

    // ---- prefetch B slice 0 (chunk 0, k 0..63): 512 rows x 128B ----
    {
        #pragma unroll
        for (int i = 0; i < 8; ++i) {
            const int j = tid + i * THREADS;          // 4096 granules
            const int m = j >> 3, g = j & 7;
            cp_async16(smx + SM_B + m * 128 + (((uint32_t)g ^ (uint32_t)(m & 7)) << 4),
                       g_memh + (size_t)m * 512 + (size_t)g * 16);
        }
        CP_COMMIT();
    }

    // ---- x prologue: full norms (all 512 k), store only k<256 to smem ----
    {
        const float* xb = x + (size_t)b * CDIM * HWDIM + n0;
        const int px4 = lane << 2;
        float s1 = 0.f, s2 = 0.f;
        #pragma unroll 4
        for (int it = 0; it < 16; ++it) {             // k < 256: ss + store
            const int k = wid + it * 16;
            const float4 v = *(const float4*)(xb + (size_t)k * HWDIM + px4);
            s1 += v.x * v.x + v.y * v.y + v.z * v.z + v.w * v.w;
            uint32_t p0 = __half_as_ushort(__float2half_rn(v.x)) |
                          ((uint32_t)__half_as_ushort(__float2half_rn(v.y)) << 16);
            uint32_t p1 = __half_as_ushort(__float2half_rn(v.z)) |
                          ((uint32_t)__half_as_ushort(__float2half_rn(v.w)) << 16);
            const uint32_t a = (uint32_t)(k << 8) + (((uint32_t)(px4 << 1)) ^ ((k & 7) << 4));
            *(uint2*)(smem + SM_X + a) = make_uint2(p0, p1);
        }
        #pragma unroll 4
        for (int it = 16; it < 32; ++it) {            // k >= 256: tail ss only
            const int k = wid + it * 16;
            const float4 v = *(const float4*)(xb + (size_t)k * HWDIM + px4);
            s2 += v.x * v.x + v.y * v.y + v.z * v.z + v.w * v.w;
        }
        // fold 4 per-px sums by lane groups: each lane owns px4..px4+3 jointly
        // with other warps -> atomics (px norm needs sum over k which is
        // distributed across warps). Per-lane partial covers 4 pixels equally.
        atomicAdd(&s_n2[px4 + 0], 0.0f);  // keep slot warm (no-op)
        // accumulate per pixel: each lane's s1/s2 mixes 4 pixels' squares; we
        // must split per pixel -> redo with per-pixel accumulators instead:
        (void)s1; (void)s2;
    }
    // NOTE: per-pixel norms need per-pixel accumulation; do it cleanly here.
    {
        const float* xb = x + (size_t)b * CDIM * HWDIM + n0;
        const int px4 = lane << 2;
        float a1[4] = {0.f, 0.f, 0.f, 0.f};
        float a2[4] = {0.f, 0.f, 0.f, 0.f};
        #pragma unroll 4
        for (int it = 0; it < 32; ++it) {
            const int k = wid + it * 16;
            const float4 v = *(const float4*)(xb + (size_t)k * HWDIM + px4);
            float* acc = (it < 16) ? a1 : a2;
            acc[0] += v.x * v.x; acc[1] += v.y * v.y;
            acc[2] += v.z * v.z; acc[3] += v.w * v.w;
        }
        #pragma unroll
        for (int j = 0; j < 4; ++j) {
            atomicAdd(&s_n2[px4 + j], a1[j] + a2[j]);
            atomicAdd(&s_t2[px4 + j], a2[j]);
        }
    }

    // ---- lane addressing ----
    const int lr = lane & 7;
    const int lh = (lane >> 3) & 1;
    const int lq = (lane >> 4) & 1;
    const uint32_t a_hi = (uint32_t)(lane >> 4);
    uint32_t aB[4];
    #pragma unroll
    for (int mt = 0; mt < 4; ++mt)
        aB[mt] = (uint32_t)((warp_m * 64 + mt * 16 + (lane & 15)) << 7);  // *128B
    const uint32_t krow = (uint32_t)(lr + lh * 8);
    uint32_t pxoff[4];
    #pragma unroll
    for (int G = 0; G < 4; ++G)
        pxoff[G] = ((uint32_t)((warp_n * 64 + lq * 8 + G * 16) << 1)) ^ ((uint32_t)lr << 4);

    uint32_t rmax2[8];
    {
        const __half2 ninf = __float2half2_rn(-60000.0f);
        #pragma unroll
        for (int s = 0; s < 8; ++s) rmax2[s] = *(const uint32_t*)&ninf;
    }
    uint32_t d[4][8][2];

    // ---- mainloop: 8 slices = 2 chunks x 4 k-slices of 64 ----
    for (int ts = 0; ts < 8; ++ts) {
        if (ts + 1 < 8) {
            const int nx2 = ts + 1;
            const unsigned char* src = g_memh +
                (size_t)(nx2 >> 2) * (512 * 512) + (size_t)(nx2 & 3) * 128;
            const uint32_t dstb = smx + SM_B + (nx2 & 1) * 65536;
            #pragma unroll
            for (int i = 0; i < 8; ++i) {
                const int j = tid + i * THREADS;
                const int m = j >> 3, g = j & 7;
                cp_async16(dstb + m * 128 + (((uint32_t)g ^ (uint32_t)(m & 7)) << 4),
                           src + (size_t)m * 512 + (size_t)g * 16);
            }
            CP_COMMIT();
            CP_WAIT(1);
        } else {
            CP_WAIT(0);
        }
        __syncthreads();

        if ((ts & 3) == 0) {
            #pragma unroll
            for (int mt = 0; mt < 4; ++mt)
                #pragma unroll
                for (int nt = 0; nt < 8; ++nt)
                    d[mt][nt][0] = d[mt][nt][1] = 0u;
        }

        const uint32_t abuf = smx + SM_B + (ts & 1) * 65536;
        const uint32_t kbase = (uint32_t)((ts & 3) * 64);

        #pragma unroll
        for (int ks = 0; ks < 4; ++ks) {
            uint32_t a[4][4];
            #pragma unroll
            for (int mt = 0; mt < 4; ++mt)
                ldsm_x4(a[mt][0], a[mt][1], a[mt][2], a[mt][3],
                        abuf + aB[mt] +
                        (((((uint32_t)ks << 1) | a_hi) ^ ((aB[mt] >> 7) & 7)) << 4));
            uint32_t bq[4][4];
            const uint32_t brow = smx + SM_X + ((kbase + (uint32_t)(ks * 16) + krow) << 8);
            #pragma unroll
            for (int G = 0; G < 4; ++G)
                ldsm_x4t(bq[G][0], bq[G][1], bq[G][2], bq[G][3], brow + pxoff[G]);
            #pragma unroll
            for (int mt = 0; mt < 4; ++mt)
                #pragma unroll
                for (int nt = 0; nt < 8; ++nt)
                    mma_h(d[mt][nt][0], d[mt][nt][1],
                          a[mt][0], a[mt][1], a[mt][2], a[mt][3],
                          bq[nt >> 1][(nt & 1) * 2], bq[nt >> 1][(nt & 1) * 2 + 1]);
        }

        if ((ts & 3) == 3) {             // chunk done: pure max fold (no idx)
            #pragma unroll
            for (int nt = 0; nt < 8; ++nt)
                #pragma unroll
                for (int mt = 0; mt < 4; ++mt)
                    rmax2[nt] = hmax2u(rmax2[nt], hmax2u(d[mt][nt][0], d[mt][nt][1]));
        }
        __syncthreads();
    }

    // ---- cross-lane max (rows live on lane>>2; cols on lane&3) ----
    #pragma unroll
    for (int o = 4; o <= 16; o <<= 1)
        #pragma unroll
        for (int s = 0; s < 8; ++s)
            rmax2[s] = hmax2u(rmax2[s], __shfl_xor_sync(0xffffffffu, rmax2[s], o));
    if (lane < 4) {
        #pragma unroll
        for (int nt = 0; nt < 8; ++nt) {
            const float2 f = __half22float2(*(const __half2*)&rmax2[nt]);
            const int px = warp_n * 64 + (nt >> 1) * 16 + (nt & 1) * 8 + lane * 2;
            s_rm[warp_m * 128 + px]     = f.x;
            s_rm[warp_m * 128 + px + 1] = f.y;
        }
    }
    __syncthreads();

    // ---- per-pixel screen: dot1max + ||x2||*Bmax > 0.75*||x|| ? ----
    const float bmax = g_bmax;
    if (tid < TILE_PX) {
        float bv = s_rm[tid];
        #pragma unroll
        for (int g = 1; g < 8; ++g) bv = fmaxf(bv, s_rm[g * 128 + tid]);
        const float nx = fmaxf(sqrtf(s_n2[tid]), 1e-12f);
        const float xt = sqrtf(s_t2[tid]);
        s_flag[tid] = (bv + xt * bmax > 0.75f * nx) ? 1 : 0;
        s_pass[tid] = 0;
        s_idx[tid]  = 0;
    }
    __syncthreads();

    // ---- exact fp32 path for flagged pixels (expected: none) ----
    for (int px = 0; px < TILE_PX; ++px) {
        if (!s_flag[px]) continue;
        for (int c = tid; c < CDIM; c += THREADS)
            s_xv[c] = x[(size_t)b * CDIM * HWDIM + (size_t)c * HWDIM + n0 + px];
        if (tid == 0) { *s_bestu = 0u; *s_besti = 0x7fffffff; }
        __syncthreads();
        float lb = -3.0e38f; int li = 0x7fffffff;
        #pragma unroll 1
        for (int mm = tid * 2; mm < tid * 2 + 2; ++mm) {
            const float* mr = memory + (size_t)mm * CDIM;
            float dot = 0.f, nn = 0.f;
            for (int c = 0; c < CDIM; ++c) { const float mv = mr[c]; dot += s_xv[c] * mv; nn += mv * mv; }
            const float v = dot / fmaxf(sqrtf(nn), 1e-12f);
            if (v > lb) { lb = v; li = mm; }
        }
        unsigned enc = __float_as_uint(lb);
        enc = (enc & 0x80000000u) ? ~enc : (enc | 0x80000000u);
        atomicMax(s_bestu, enc);
        __syncthreads();
        if (enc == *s_bestu) atomicMin(s_besti, li);
        __syncthreads();
        if (tid == 0) {
            unsigned u = *s_bestu;
            const float bvf = __uint_as_float((u & 0x80000000u) ? (u & 0x7fffffffu) : ~u);
            const float nx = fmaxf(sqrtf(s_n2[px]), 1e-12f);
            s_pass[px] = (bvf > THRESH * nx) ? 1 : 0;
            s_idx[px]  = *s_besti;
        }
        __syncthreads();
    }
    __syncthreads();

    // ---- writeback: full tile, coalesced ----
    {
        const int pxl = tid & 127;
        const int c0  = tid >> 7;
        const int pass = s_pass[pxl];
        const float* mrow = memory + (size_t)s_idx[pxl] * CDIM;
        float* ob = out + (size_t)b * CDIM * HWDIM + n0 + pxl;
        #pragma unroll 8
        for (int c = c0; c < CDIM; c += 4)
            ob[(size_t)c * HWDIM] = pass ? mrow[c] : 0.0f;
    }
}

// ---------------------------------------------------------------------------
extern "C" void kernel_launch(void* const* d_in, const int* in_sizes, int n_in,
                              void* d_out, int out_size) {
    const float* x      = (const float*)d_in[0];
    const float* memory = (const float*)d_in[1];
    float* out          = (float*)d_out;

    cudaFuncSetAttribute(hardmem_main_kernel,
                         cudaFuncAttributeMaxDynamicSharedMemorySize, SM_TOTAL);

    normalize_mem_kernel<<<MMEM, 128>>>(memory);
    hardmem_main_kernel<<<32 * (HWDIM / TILE_PX), THREADS, SM_TOTAL>>>(x, memory, out);
}